// round 9
// baseline (speedup 1.0000x reference)
#include <cuda_runtime.h>
#include <cstdint>

#define BSZ 4
#define D 16
#define MDIM 32
#define LTOT 81
#define NBLK 512
#define NPASS2 (LTOT * BSZ)   // 324

#define ADD4(a, v) do { (a).x += (v).x; (a).y += (v).y; (a).z += (v).z; (a).w += (v).w; } while (0)

// Q[slab][jj][m], slab=(b,p1,p2) 0..1023, jj=j3*3+j4. 1.18 MB.
__device__ float g_Q[BSZ * D * D * 9 * MDIM];
__device__ float g_H[BSZ * LTOT];
__device__ unsigned int g_c1 = 0;
__device__ unsigned int g_c2 = 0;

__device__ __forceinline__ uint32_t smem_u32(const void* p) {
    uint32_t a;
    asm("{ .reg .u64 t; cvta.to.shared.u64 t, %1; cvt.u32.u64 %0, t; }" : "=r"(a) : "l"(p));
    return a;
}
__device__ __forceinline__ void mbar_init(uint32_t mbar, uint32_t cnt) {
    asm volatile("mbarrier.init.shared.b64 [%0], %1;" :: "r"(mbar), "r"(cnt) : "memory");
}
__device__ __forceinline__ void mbar_expect_tx(uint32_t mbar, uint32_t bytes) {
    asm volatile("mbarrier.arrive.expect_tx.shared.b64 _, [%0], %1;" :: "r"(mbar), "r"(bytes) : "memory");
}
__device__ __forceinline__ void mbar_wait(uint32_t mbar, uint32_t parity) {
    asm volatile(
        "{\n\t.reg .pred P;\n\t"
        "WAIT_%=:\n\t"
        "mbarrier.try_wait.parity.acquire.cta.shared::cta.b64 P, [%0], %1, 0x989680;\n\t"
        "@!P bra WAIT_%=;\n\t}"
        :: "r"(mbar), "r"(parity) : "memory");
}
__device__ __forceinline__ void bulk_g2s(uint32_t dst, const void* src, uint32_t bytes, uint32_t mbar) {
    asm volatile(
        "cp.async.bulk.shared::cta.global.mbarrier::complete_tx::bytes [%0], [%1], %2, [%3];"
        :: "r"(dst), "l"(src), "r"(bytes), "r"(mbar) : "memory");
}
__device__ __forceinline__ void fence_proxy_async_cta() {
    asm volatile("fence.proxy.async.shared::cta;" ::: "memory");
}

// ---------------------------------------------------------------------------
// Fused kernel: 512 CTAs x 128 threads, ALL co-resident (smem 39KB -> 5/SM).
// Phase A (TMA): CTA k reduces slabs 2k, 2k+1 via 4-stage 8KB ring -> g_Q.
// grid barrier 1
// Phase B: blocks 0..323 compute H[b,c] from L2-hot g_Q.
// grid barrier 2
// Phase C: block 0: out[b,n] = K * sum_c H[b,c]*Acoeff[n,c]; reset counters.
// ---------------------------------------------------------------------------
#define CHUNK_BYTES 8192
__global__ void __launch_bounds__(128)
fused_kernel(const char* __restrict__ arr,
             const float* __restrict__ Mmat,
             const float* __restrict__ Acoeff,
             const float* __restrict__ Bbasis,
             float* __restrict__ out) {
    __shared__ __align__(16) float buf[4][4 * 16 * 32];     // 4 x 8KB ring
    __shared__ float4 S[16][3][8];                           // [p4][j3][m4] 6KB
    __shared__ __align__(8) unsigned long long mbar[4];
    __shared__ float E_s[32];
    __shared__ float part[4][32];

    const int t    = threadIdx.x;
    const int m4   = t & 7;
    const int p4   = t >> 3;          // 0..15
    const int lane = t & 31;
    const int wp   = t >> 5;

    uint32_t mb[4];
#pragma unroll
    for (int q = 0; q < 4; ++q) mb[q] = smem_u32(&mbar[q]);

    if (t == 0) {
#pragma unroll
        for (int q = 0; q < 4; ++q) mbar_init(mb[q], 1);
    }
    __syncthreads();

    // ---------------- Phase A ----------------
    const int slab0 = blockIdx.x * 2;
    const char* __restrict__ src0 = arr + (size_t)slab0 * 32768;

    if (t == 0) {
#pragma unroll
        for (int q = 0; q < 4; ++q) {
            mbar_expect_tx(mb[q], CHUNK_BYTES);
            bulk_g2s(smem_u32(&buf[q][0]), src0 + q * CHUNK_BYTES, CHUNK_BYTES, mb[q]);
        }
    }

#pragma unroll
    for (int s = 0; s < 2; ++s) {
        const int slab = slab0 + s;
        float4 t0 = {0.f,0.f,0.f,0.f}, t1 = t0, t2 = t0;

#pragma unroll
        for (int q = 0; q < 4; ++q) {
            mbar_wait(mb[q], (uint32_t)s);

            const float4* __restrict__ bp = (const float4*)(&buf[q][0]) + p4 * 8 + m4;
#pragma unroll
            for (int k = 0; k < 4; ++k) {
                const int p3 = q * 4 + k;           // compile-time
                float4 v = bp[k * 128];
                if (p3 >= 1) {
                    const int ja = (p3 - 1) % 3;
                    if (ja == 0) ADD4(t0, v); else if (ja == 1) ADD4(t1, v); else ADD4(t2, v);
                }
                if (p3 <= 14) {
                    const int jb = p3 % 3;
                    if (jb == 0) ADD4(t0, v); else if (jb == 1) ADD4(t1, v); else ADD4(t2, v);
                }
            }
            __syncthreads();                        // all reads of buf[q] done
            if (s == 0 && t == 0) {                 // refill with slab1 chunk q
                fence_proxy_async_cta();
                mbar_expect_tx(mb[q], CHUNK_BYTES);
                bulk_g2s(smem_u32(&buf[q][0]),
                         src0 + 32768 + q * CHUNK_BYTES, CHUNK_BYTES, mb[q]);
            }
        }

        S[p4][0][m4] = t0;
        S[p4][1][m4] = t1;
        S[p4][2][m4] = t2;
        __syncthreads();

        if (t < 72) {               // t = jj*8 + mm : reduce p4 -> j4 classes
            const int mm = t & 7;
            const int jj = t >> 3;  // j3*3 + j4
            const int j4 = jj % 3;
            const int j3 = jj / 3;
            float4 qv = {0.f,0.f,0.f,0.f};
#pragma unroll
            for (int i = 0; i < 10; ++i) {
                const int p = 3 * (i >> 1) + j4 + (i & 1);
                ADD4(qv, S[p][j3][mm]);
            }
            ((float4*)g_Q)[slab * 72 + jj * 8 + mm] = qv;
        }
        __syncthreads();
    }

    // ---------------- grid barrier 1 ----------------
    if (t == 0) {
        __threadfence();
        atomicAdd(&g_c1, 1u);
    }
    if (blockIdx.x >= NPASS2) return;

    if (t == 0) {
        while (atomicAdd(&g_c1, 0u) < (unsigned)NBLK) __nanosleep(64);
    }
    __syncthreads();
    __threadfence();

    // ---------------- Phase B: one (c,b) per block ----------------
    const int c = blockIdx.x % LTOT;
    const int b = blockIdx.x / LTOT;

    const int j4 = c % 3;
    const int j3 = (c / 3) % 3;
    const int j2 = (c / 9) % 3;
    const int j1 = c / 27;
    const int jj = j3 * 3 + j4;

    if (t < 32) {
        float e = 0.f;
#pragma unroll
        for (int n = 0; n < MDIM; ++n)
            e += Bbasis[c * MDIM + n] * Mmat[n * MDIM + t];
        E_s[t] = e;
    }

    float g = 0.f;
#pragma unroll
    for (int k = wp; k < 100; k += 4) {        // 25 independent loads/warp
        const int i1 = k / 10;
        const int i2 = k % 10;
        const int p1 = 3 * (i1 >> 1) + j1 + (i1 & 1);
        const int p2 = 3 * (i2 >> 1) + j2 + (i2 & 1);
        g += g_Q[(((b * D + p1) * D + p2) * 9 + jj) * MDIM + lane];
    }
    part[wp][lane] = g;
    __syncthreads();

    if (wp == 0) {
        float G = part[0][lane] + part[1][lane] + part[2][lane] + part[3][lane];
        float h = E_s[lane] * G;
#pragma unroll
        for (int o = 16; o; o >>= 1)
            h += __shfl_xor_sync(0xffffffffu, h, o);
        if (lane == 0) g_H[b * LTOT + c] = h;
    }

    // ---------------- grid barrier 2 ----------------
    if (t == 0) {
        __threadfence();
        atomicAdd(&g_c2, 1u);
    }
    if (blockIdx.x != 0) return;

    if (t == 0) {
        while (atomicAdd(&g_c2, 0u) < (unsigned)NPASS2) __nanosleep(64);
    }
    __syncthreads();
    __threadfence();

    // ---------------- Phase C: block 0 ----------------
    {
        const int bb = t >> 5;
        const int n  = t & 31;
        const float K = 1.0f / (16.0f * 50625.0f);
        float sum = 0.f;
#pragma unroll
        for (int cc = 0; cc < LTOT; ++cc)
            sum += g_H[bb * LTOT + cc] * Acoeff[n * LTOT + cc];
        out[bb * MDIM + n] = sum * K;
    }
    __syncthreads();
    if (t == 0) {                    // reset for next graph replay
        g_c1 = 0;
        g_c2 = 0;
        __threadfence();
    }
}

extern "C" void kernel_launch(void* const* d_in, const int* in_sizes, int n_in,
                              void* d_out, int out_size) {
    const char* arr     = (const char*)d_in[0];    // [4,16,16,16,16,32] f32
    const float* Mmat   = (const float*)d_in[1];   // [32,32]
    const float* Acoeff = (const float*)d_in[2];   // [32,81]
    const float* Bbasis = (const float*)d_in[3];   // [81,32]
    float* out = (float*)d_out;                    // [4,32]

    fused_kernel<<<NBLK, 128>>>(arr, Mmat, Acoeff, Bbasis, out);
}